// round 5
// baseline (speedup 1.0000x reference)
#include <cuda_runtime.h>
#include <stdint.h>

// Problem constants (fixed by the dataset)
#define NMAX   50000
#define EMAX   800000
#define GMAX   64
#define HID    128
#define OUTF   64

// ---------------- device scratch (no allocations allowed) ----------------
__device__ int                    g_cnt[NMAX];
__device__ int                    g_rowptr[NMAX + 1];
__device__ int                    g_pos[NMAX];
__device__ int                    g_csr_src[EMAX];
__device__ float                  g_csr_w[EMAX];
__device__ float                  g_dinv[NMAX];
__device__ __align__(16) float    g_T[NMAX * HID];   // GEMM outputs / messages
__device__ __align__(16) float    g_H[NMAX * HID];   // activations
__device__ float                  g_poolsum[GMAX * OUTF];
__device__ int                    g_gcnt[GMAX];

// ---------------- setup kernels ----------------

__global__ void k_zero(int n) {
    int i = blockIdx.x * blockDim.x + threadIdx.x;
    if (i < n) g_cnt[i] = 0;
    if (i < GMAX * OUTF) g_poolsum[i] = 0.f;
    if (i < GMAX) g_gcnt[i] = 0;
}

__global__ void k_hist(const int* __restrict__ ei, int e) {
    int i = blockIdx.x * blockDim.x + threadIdx.x;
    if (i < e) {
        int d = ei[e + i];   // dst row of edge_index [2,E]
        atomicAdd(&g_cnt[d], 1);
    }
}

__global__ void k_dinv(int n) {
    int i = blockIdx.x * blockDim.x + threadIdx.x;
    if (i < n) g_dinv[i] = rsqrtf((float)(g_cnt[i] + 1));  // +1 self loop
}

// single-block exclusive scan of g_cnt -> g_rowptr / g_pos
__global__ void k_scan(int n, int e_total) {
    __shared__ int warp_sums[32];
    __shared__ int s_carry;
    int tid = threadIdx.x, lane = tid & 31, wid = tid >> 5;
    if (tid == 0) s_carry = 0;
    __syncthreads();
    for (int base = 0; base < n; base += 1024) {
        int i = base + tid;
        int v = (i < n) ? g_cnt[i] : 0;
        int x = v;
        #pragma unroll
        for (int o = 1; o < 32; o <<= 1) {
            int y = __shfl_up_sync(0xffffffffu, x, o);
            if (lane >= o) x += y;
        }
        if (lane == 31) warp_sums[wid] = x;
        __syncthreads();
        if (wid == 0) {
            int w = warp_sums[lane];
            #pragma unroll
            for (int o = 1; o < 32; o <<= 1) {
                int y = __shfl_up_sync(0xffffffffu, w, o);
                if (lane >= o) w += y;
            }
            warp_sums[lane] = w;
        }
        __syncthreads();
        int warp_off = (wid > 0) ? warp_sums[wid - 1] : 0;
        int incl = x + warp_off;
        int carry = s_carry;
        int excl = carry + incl - v;
        if (i < n) { g_rowptr[i] = excl; g_pos[i] = excl; }
        __syncthreads();
        if (tid == 1023) s_carry = carry + warp_sums[31];
        __syncthreads();
    }
    if (tid == 0) g_rowptr[n] = e_total;
}

__global__ void k_fill(const int* __restrict__ ei, int e) {
    int i = blockIdx.x * blockDim.x + threadIdx.x;
    if (i < e) {
        int s = ei[i];
        int d = ei[e + i];
        int idx = atomicAdd(&g_pos[d], 1);
        g_csr_src[idx] = s;
        g_csr_w[idx]   = g_dinv[s] * g_dinv[d];
    }
}

__global__ void k_gcnt(const int* __restrict__ batch, int n) {
    int i = blockIdx.x * blockDim.x + threadIdx.x;
    if (i < n) atomicAdd(&g_gcnt[batch[i]], 1);
}

// ---------------- layer 1: aggregate raw 7-wide features ----------------
// m[i] = x[i]*dinv_i^2 + sum_{e: dst=i} w_e * x[src_e], stored stride-8 in g_T
__global__ void k_agg7(const float* __restrict__ x, int n) {
    int gid = blockIdx.x * blockDim.x + threadIdx.x;
    int node = gid >> 3;
    int f = gid & 7;
    if (node >= n) return;
    float di = g_dinv[node];
    float acc = (f < 7) ? x[node * 7 + f] * di * di : 0.f;
    int beg = g_rowptr[node], end = g_rowptr[node + 1];
    for (int e = beg; e < end; ++e) {
        int s = g_csr_src[e];
        float w = g_csr_w[e];
        if (f < 7) acc += w * x[s * 7 + f];
    }
    if (f < 7) g_T[node * 8 + f] = acc;
}

// h1 = relu(m @ W1 + b1), m stride-8 in g_T, out to g_H (N x 128)
__global__ void k_gemm1(const float* __restrict__ W1, const float* __restrict__ b1, int n) {
    int gid = blockIdx.x * blockDim.x + threadIdx.x;
    int node = gid >> 7;
    int c = gid & 127;
    if (node >= n) return;
    const float* m = g_T + node * 8;
    float acc = b1[c];
    #pragma unroll
    for (int k = 0; k < 7; ++k) acc = fmaf(m[k], W1[k * 128 + c], acc);
    g_H[node * 128 + c] = fmaxf(acc, 0.f);
}

// ---------------- dense GEMM: g_T[n,NOUT] = g_H[n,128] @ B[128,NOUT] ----------------
template<int NOUT>
__global__ __launch_bounds__(256)
void k_gemm(const float* __restrict__ B, int n) {
    constexpr int K = 128, KT = 32, BN = 64;
    constexpr int CG = NOUT / 4;       // col groups (float4)
    constexpr int TR = 256 / CG;       // thread rows
    constexpr int RN = BN / TR;        // nodes per thread
    __shared__ float sA[BN][KT + 1];
    __shared__ float sB[KT][NOUT];
    int tid = threadIdx.x;
    int tx = tid % CG, ty = tid / CG;
    int nodeBase = blockIdx.x * BN;
    float acc[RN][4];
    #pragma unroll
    for (int r = 0; r < RN; ++r) { acc[r][0] = acc[r][1] = acc[r][2] = acc[r][3] = 0.f; }

    for (int k0 = 0; k0 < K; k0 += KT) {
        for (int i = tid; i < BN * KT; i += 256) {
            int r = i / KT, c = i % KT;
            int nd = nodeBase + r;
            sA[r][c] = (nd < n) ? g_H[nd * K + k0 + c] : 0.f;
        }
        for (int i = tid; i < KT * NOUT; i += 256) {
            int r = i / NOUT, c = i % NOUT;
            sB[r][c] = B[(k0 + r) * NOUT + c];
        }
        __syncthreads();
        #pragma unroll
        for (int kk = 0; kk < KT; ++kk) {
            float4 wv = *reinterpret_cast<const float4*>(&sB[kk][tx * 4]);
            #pragma unroll
            for (int r = 0; r < RN; ++r) {
                float a = sA[ty + r * TR][kk];
                acc[r][0] = fmaf(a, wv.x, acc[r][0]);
                acc[r][1] = fmaf(a, wv.y, acc[r][1]);
                acc[r][2] = fmaf(a, wv.z, acc[r][2]);
                acc[r][3] = fmaf(a, wv.w, acc[r][3]);
            }
        }
        __syncthreads();
    }
    #pragma unroll
    for (int r = 0; r < RN; ++r) {
        int nd = nodeBase + ty + r * TR;
        if (nd < n)
            *reinterpret_cast<float4*>(&g_T[nd * NOUT + tx * 4]) =
                make_float4(acc[r][0], acc[r][1], acc[r][2], acc[r][3]);
    }
}

// ---------------- sparse aggregation of transformed features ----------------
// reads g_T; writes g_H (TO_H) or `out` param. Optional relu / pool atomics.
template<int F, bool RELU, bool POOL, bool TO_H>
__global__ __launch_bounds__(256)
void k_agg(const float* __restrict__ bias, float* __restrict__ out,
           const int* __restrict__ batch, int n) {
    constexpr int LPN = F / 4;   // float4 lanes per node
    int gid = blockIdx.x * blockDim.x + threadIdx.x;
    int node = gid / LPN;
    int l = gid % LPN;
    if (node >= n) return;
    float di = g_dinv[node];
    float w0 = di * di;
    const float4* T4 = reinterpret_cast<const float4*>(g_T);
    float4 v = T4[node * LPN + l];
    float4 acc = make_float4(v.x * w0, v.y * w0, v.z * w0, v.w * w0);
    int e = g_rowptr[node], end = g_rowptr[node + 1];
    for (; e + 1 < end; e += 2) {
        int   s0 = g_csr_src[e],     s1 = g_csr_src[e + 1];
        float w1 = g_csr_w[e];
        float w2 = g_csr_w[e + 1];
        float4 t0 = T4[s0 * LPN + l];
        float4 t1 = T4[s1 * LPN + l];
        acc.x = fmaf(w1, t0.x, acc.x); acc.y = fmaf(w1, t0.y, acc.y);
        acc.z = fmaf(w1, t0.z, acc.z); acc.w = fmaf(w1, t0.w, acc.w);
        acc.x = fmaf(w2, t1.x, acc.x); acc.y = fmaf(w2, t1.y, acc.y);
        acc.z = fmaf(w2, t1.z, acc.z); acc.w = fmaf(w2, t1.w, acc.w);
    }
    if (e < end) {
        int s0 = g_csr_src[e]; float w1 = g_csr_w[e];
        float4 t0 = T4[s0 * LPN + l];
        acc.x = fmaf(w1, t0.x, acc.x); acc.y = fmaf(w1, t0.y, acc.y);
        acc.z = fmaf(w1, t0.z, acc.z); acc.w = fmaf(w1, t0.w, acc.w);
    }
    float4 b = reinterpret_cast<const float4*>(bias)[l];
    acc.x += b.x; acc.y += b.y; acc.z += b.z; acc.w += b.w;
    if (RELU) {
        acc.x = fmaxf(acc.x, 0.f); acc.y = fmaxf(acc.y, 0.f);
        acc.z = fmaxf(acc.z, 0.f); acc.w = fmaxf(acc.w, 0.f);
    }
    if (TO_H)
        reinterpret_cast<float4*>(g_H)[node * LPN + l] = acc;
    else
        reinterpret_cast<float4*>(out)[node * LPN + l] = acc;
    if (POOL) {
        int gidx = batch[node];
        atomicAdd(&g_poolsum[gidx * F + l * 4 + 0], acc.x);
        atomicAdd(&g_poolsum[gidx * F + l * 4 + 1], acc.y);
        atomicAdd(&g_poolsum[gidx * F + l * 4 + 2], acc.z);
        atomicAdd(&g_poolsum[gidx * F + l * 4 + 3], acc.w);
    }
}

__global__ void k_pooldiv(float* __restrict__ out, int g) {
    int i = blockIdx.x * blockDim.x + threadIdx.x;
    if (i < g * OUTF) {
        float c = (float)g_gcnt[i / OUTF];
        out[i] = g_poolsum[i] / fmaxf(c, 1.f);
    }
}

// ---------------- launch ----------------
extern "C" void kernel_launch(void* const* d_in, const int* in_sizes, int n_in,
                              void* d_out, int out_size) {
    const float* x     = (const float*)d_in[0];
    const int*   ei    = (const int*)d_in[1];    // int32! (jax x64 disabled)
    const int*   batch = (const int*)d_in[2];    // int32!
    const float* W1 = (const float*)d_in[3];
    const float* b1 = (const float*)d_in[4];
    const float* W2 = (const float*)d_in[5];
    const float* b2 = (const float*)d_in[6];
    const float* W3 = (const float*)d_in[7];
    const float* b3 = (const float*)d_in[8];
    float* out = (float*)d_out;

    int n = in_sizes[0] / 7;
    int e = in_sizes[1] / 2;
    int g = out_size / OUTF - n;
    if (g < 0) g = 0;

    const int T = 256;
    // --- degree / CSR build ---
    k_zero<<<(n + T - 1) / T, T>>>(n);
    k_hist<<<(e + T - 1) / T, T>>>(ei, e);
    k_dinv<<<(n + T - 1) / T, T>>>(n);
    k_scan<<<1, 1024>>>(n, e);
    k_fill<<<(e + T - 1) / T, T>>>(ei, e);
    if (g > 0) k_gcnt<<<(n + T - 1) / T, T>>>(batch, n);

    // --- layer 1: aggregate 7-wide, then transform+bias+relu ---
    k_agg7<<<(n * 8 + T - 1) / T, T>>>(x, n);
    k_gemm1<<<(n * 128 + T - 1) / T, T>>>(W1, b1, n);

    // --- layer 2: transform (g_H -> g_T), aggregate+bias+relu (g_T -> g_H) ---
    k_gemm<128><<<(n + 63) / 64, 256>>>(W2, n);
    k_agg<128, true, false, true><<<(n * 32 + T - 1) / T, T>>>(b2, nullptr, batch, n);

    // --- layer 3: transform 64-wide (g_H -> g_T), aggregate+bias (+pool) -> out ---
    k_gemm<64><<<(n + 63) / 64, 256>>>(W3, n);
    if (g > 0) {
        k_agg<64, false, true, false><<<(n * 16 + T - 1) / T, T>>>(b3, out, batch, n);
        k_pooldiv<<<(g * OUTF + T - 1) / T, T>>>(out + (size_t)n * OUTF, g);
    } else {
        k_agg<64, false, false, false><<<(n * 16 + T - 1) / T, T>>>(b3, out, batch, n);
    }
}

// round 6
// speedup vs baseline: 1.0894x; 1.0894x over previous
#include <cuda_runtime.h>
#include <stdint.h>

// Problem constants (fixed by the dataset)
#define NMAX   50000
#define EMAX   800000
#define GMAX   64
#define HID    128
#define OUTF   64

// ---------------- device scratch (no allocations allowed) ----------------
__device__ int                    g_cnt[NMAX];
__device__ int                    g_rowptr[NMAX + 1];
__device__ int                    g_pos[NMAX];
__device__ int                    g_blocksum[64];
__device__ int                    g_csr_src[EMAX];
__device__ float                  g_csr_w[EMAX];
__device__ float                  g_dinv[NMAX];
__device__ __align__(16) float    g_T[NMAX * HID];   // GEMM outputs / messages
__device__ __align__(16) float    g_H[NMAX * HID];   // activations
__device__ float                  g_poolsum[GMAX * OUTF];
__device__ int                    g_gcnt[GMAX];

// ---------------- setup kernels ----------------

__global__ void k_zero(int n) {
    int i = blockIdx.x * blockDim.x + threadIdx.x;
    if (i < n) g_cnt[i] = 0;
    if (i < GMAX * OUTF) g_poolsum[i] = 0.f;
    if (i < GMAX) g_gcnt[i] = 0;
}

__global__ void k_hist(const int* __restrict__ ei, int e) {
    int i = blockIdx.x * blockDim.x + threadIdx.x;
    if (i < e) {
        int d = ei[e + i];   // dst row of edge_index [2,E]
        atomicAdd(&g_cnt[d], 1);
    }
}

// ---------------- hierarchical exclusive scan of g_cnt ----------------
// phase 1: per-block (1024 elems) local exclusive scan -> g_rowptr (partial),
//          block total -> g_blocksum; also computes g_dinv (reads g_cnt anyway).
__global__ __launch_bounds__(1024)
void k_scan1(int n) {
    __shared__ int warp_sums[32];
    int tid = threadIdx.x, lane = tid & 31, wid = tid >> 5;
    int i = blockIdx.x * 1024 + tid;
    int v = (i < n) ? g_cnt[i] : 0;
    if (i < n) g_dinv[i] = rsqrtf((float)(v + 1));  // +1 self loop
    int x = v;
    #pragma unroll
    for (int o = 1; o < 32; o <<= 1) {
        int y = __shfl_up_sync(0xffffffffu, x, o);
        if (lane >= o) x += y;
    }
    if (lane == 31) warp_sums[wid] = x;
    __syncthreads();
    if (wid == 0) {
        int w = warp_sums[lane];
        #pragma unroll
        for (int o = 1; o < 32; o <<= 1) {
            int y = __shfl_up_sync(0xffffffffu, w, o);
            if (lane >= o) w += y;
        }
        warp_sums[lane] = w;
    }
    __syncthreads();
    int off = (wid > 0) ? warp_sums[wid - 1] : 0;
    if (i < n) g_rowptr[i] = x + off - v;          // local exclusive
    if (tid == 1023) g_blocksum[blockIdx.x] = x + off;  // block total
}

// phase 2: exclusive scan of up to 64 block totals (one block of 64 threads)
__global__ void k_scan2(int nb, int n, int e_total) {
    __shared__ int ws[2];
    int tid = threadIdx.x, lane = tid & 31, wid = tid >> 5;
    int v = (tid < nb) ? g_blocksum[tid] : 0;
    int x = v;
    #pragma unroll
    for (int o = 1; o < 32; o <<= 1) {
        int y = __shfl_up_sync(0xffffffffu, x, o);
        if (lane >= o) x += y;
    }
    if (lane == 31) ws[wid] = x;
    __syncthreads();
    int off = (wid == 1) ? ws[0] : 0;
    if (tid < 64) g_blocksum[tid] = x + off - v;   // exclusive
    if (tid == 0) g_rowptr[n] = e_total;
}

// phase 3: add block offsets, duplicate into g_pos
__global__ void k_scan3(int n) {
    int i = blockIdx.x * blockDim.x + threadIdx.x;
    if (i < n) {
        int r = g_rowptr[i] + g_blocksum[i >> 10];
        g_rowptr[i] = r;
        g_pos[i] = r;
    }
}

__global__ void k_fill(const int* __restrict__ ei, int e) {
    int i = blockIdx.x * blockDim.x + threadIdx.x;
    if (i < e) {
        int s = ei[i];
        int d = ei[e + i];
        int idx = atomicAdd(&g_pos[d], 1);
        g_csr_src[idx] = s;
        g_csr_w[idx]   = g_dinv[s] * g_dinv[d];
    }
}

__global__ void k_gcnt(const int* __restrict__ batch, int n) {
    int i = blockIdx.x * blockDim.x + threadIdx.x;
    if (i < n) atomicAdd(&g_gcnt[batch[i]], 1);
}

// ---------------- layer 1: aggregate raw 7-wide features ----------------
// m[i] = x[i]*dinv_i^2 + sum_{e: dst=i} w_e * x[src_e], stored stride-8 in g_T
__global__ void k_agg7(const float* __restrict__ x, int n) {
    int gid = blockIdx.x * blockDim.x + threadIdx.x;
    int node = gid >> 3;
    int f = gid & 7;
    if (node >= n) return;
    float di = g_dinv[node];
    float acc = (f < 7) ? x[node * 7 + f] * di * di : 0.f;
    int beg = g_rowptr[node], end = g_rowptr[node + 1];
    for (int e = beg; e < end; ++e) {
        int s = g_csr_src[e];
        float w = g_csr_w[e];
        if (f < 7) acc += w * x[s * 7 + f];
    }
    if (f < 7) g_T[node * 8 + f] = acc;
}

// h1 = relu(m @ W1 + b1), m stride-8 in g_T, out to g_H (N x 128)
__global__ void k_gemm1(const float* __restrict__ W1, const float* __restrict__ b1, int n) {
    int gid = blockIdx.x * blockDim.x + threadIdx.x;
    int node = gid >> 7;
    int c = gid & 127;
    if (node >= n) return;
    const float* m = g_T + node * 8;
    float acc = b1[c];
    #pragma unroll
    for (int k = 0; k < 7; ++k) acc = fmaf(m[k], W1[k * 128 + c], acc);
    g_H[node * 128 + c] = fmaxf(acc, 0.f);
}

// ---------------- dense GEMM: g_T[n,NOUT] = g_H[n,128] @ B[128,NOUT] ----------------
template<int NOUT>
__global__ __launch_bounds__(256)
void k_gemm(const float* __restrict__ B, int n) {
    constexpr int K = 128, KT = 32, BN = 64;
    constexpr int CG = NOUT / 4;       // col groups (float4)
    constexpr int TR = 256 / CG;       // thread rows
    constexpr int RN = BN / TR;        // nodes per thread
    __shared__ float sA[BN][KT + 1];
    __shared__ float sB[KT][NOUT];
    int tid = threadIdx.x;
    int tx = tid % CG, ty = tid / CG;
    int nodeBase = blockIdx.x * BN;
    float acc[RN][4];
    #pragma unroll
    for (int r = 0; r < RN; ++r) { acc[r][0] = acc[r][1] = acc[r][2] = acc[r][3] = 0.f; }

    for (int k0 = 0; k0 < K; k0 += KT) {
        for (int i = tid; i < BN * KT; i += 256) {
            int r = i / KT, c = i % KT;
            int nd = nodeBase + r;
            sA[r][c] = (nd < n) ? g_H[nd * K + k0 + c] : 0.f;
        }
        for (int i = tid; i < KT * NOUT; i += 256) {
            int r = i / NOUT, c = i % NOUT;
            sB[r][c] = B[(k0 + r) * NOUT + c];
        }
        __syncthreads();
        #pragma unroll
        for (int kk = 0; kk < KT; ++kk) {
            float4 wv = *reinterpret_cast<const float4*>(&sB[kk][tx * 4]);
            #pragma unroll
            for (int r = 0; r < RN; ++r) {
                float a = sA[ty + r * TR][kk];
                acc[r][0] = fmaf(a, wv.x, acc[r][0]);
                acc[r][1] = fmaf(a, wv.y, acc[r][1]);
                acc[r][2] = fmaf(a, wv.z, acc[r][2]);
                acc[r][3] = fmaf(a, wv.w, acc[r][3]);
            }
        }
        __syncthreads();
    }
    #pragma unroll
    for (int r = 0; r < RN; ++r) {
        int nd = nodeBase + ty + r * TR;
        if (nd < n)
            *reinterpret_cast<float4*>(&g_T[nd * NOUT + tx * 4]) =
                make_float4(acc[r][0], acc[r][1], acc[r][2], acc[r][3]);
    }
}

// ---------------- sparse aggregation of transformed features ----------------
// reads g_T; writes g_H (TO_H) or `out` param. Optional relu / pool atomics.
template<int F, bool RELU, bool POOL, bool TO_H>
__global__ __launch_bounds__(256)
void k_agg(const float* __restrict__ bias, float* __restrict__ out,
           const int* __restrict__ batch, int n) {
    constexpr int LPN = F / 4;   // float4 lanes per node
    int gid = blockIdx.x * blockDim.x + threadIdx.x;
    int node = gid / LPN;
    int l = gid % LPN;
    if (node >= n) return;
    float di = g_dinv[node];
    float w0 = di * di;
    const float4* T4 = reinterpret_cast<const float4*>(g_T);
    float4 v = T4[node * LPN + l];
    float4 acc = make_float4(v.x * w0, v.y * w0, v.z * w0, v.w * w0);
    int e = g_rowptr[node], end = g_rowptr[node + 1];
    for (; e + 1 < end; e += 2) {
        int   s0 = g_csr_src[e],     s1 = g_csr_src[e + 1];
        float w1 = g_csr_w[e];
        float w2 = g_csr_w[e + 1];
        float4 t0 = T4[s0 * LPN + l];
        float4 t1 = T4[s1 * LPN + l];
        acc.x = fmaf(w1, t0.x, acc.x); acc.y = fmaf(w1, t0.y, acc.y);
        acc.z = fmaf(w1, t0.z, acc.z); acc.w = fmaf(w1, t0.w, acc.w);
        acc.x = fmaf(w2, t1.x, acc.x); acc.y = fmaf(w2, t1.y, acc.y);
        acc.z = fmaf(w2, t1.z, acc.z); acc.w = fmaf(w2, t1.w, acc.w);
    }
    if (e < end) {
        int s0 = g_csr_src[e]; float w1 = g_csr_w[e];
        float4 t0 = T4[s0 * LPN + l];
        acc.x = fmaf(w1, t0.x, acc.x); acc.y = fmaf(w1, t0.y, acc.y);
        acc.z = fmaf(w1, t0.z, acc.z); acc.w = fmaf(w1, t0.w, acc.w);
    }
    float4 b = reinterpret_cast<const float4*>(bias)[l];
    acc.x += b.x; acc.y += b.y; acc.z += b.z; acc.w += b.w;
    if (RELU) {
        acc.x = fmaxf(acc.x, 0.f); acc.y = fmaxf(acc.y, 0.f);
        acc.z = fmaxf(acc.z, 0.f); acc.w = fmaxf(acc.w, 0.f);
    }
    if (TO_H)
        reinterpret_cast<float4*>(g_H)[node * LPN + l] = acc;
    else
        reinterpret_cast<float4*>(out)[node * LPN + l] = acc;
    if (POOL) {
        int gidx = batch[node];
        atomicAdd(&g_poolsum[gidx * F + l * 4 + 0], acc.x);
        atomicAdd(&g_poolsum[gidx * F + l * 4 + 1], acc.y);
        atomicAdd(&g_poolsum[gidx * F + l * 4 + 2], acc.z);
        atomicAdd(&g_poolsum[gidx * F + l * 4 + 3], acc.w);
    }
}

__global__ void k_pooldiv(float* __restrict__ out, int g) {
    int i = blockIdx.x * blockDim.x + threadIdx.x;
    if (i < g * OUTF) {
        float c = (float)g_gcnt[i / OUTF];
        out[i] = g_poolsum[i] / fmaxf(c, 1.f);
    }
}

// ---------------- launch ----------------
extern "C" void kernel_launch(void* const* d_in, const int* in_sizes, int n_in,
                              void* d_out, int out_size) {
    const float* x     = (const float*)d_in[0];
    const int*   ei    = (const int*)d_in[1];    // int32 (jax x64 disabled)
    const int*   batch = (const int*)d_in[2];    // int32
    const float* W1 = (const float*)d_in[3];
    const float* b1 = (const float*)d_in[4];
    const float* W2 = (const float*)d_in[5];
    const float* b2 = (const float*)d_in[6];
    const float* W3 = (const float*)d_in[7];
    const float* b3 = (const float*)d_in[8];
    float* out = (float*)d_out;

    int n = in_sizes[0] / 7;
    int e = in_sizes[1] / 2;
    int g = out_size / OUTF - n;
    if (g < 0) g = 0;

    const int T = 256;
    int nb = (n + 1023) / 1024;           // scan blocks (<= 64)
    // --- degree / CSR build ---
    k_zero<<<(n + T - 1) / T, T>>>(n);
    k_hist<<<(e + T - 1) / T, T>>>(ei, e);
    k_scan1<<<nb, 1024>>>(n);             // also computes g_dinv
    k_scan2<<<1, 64>>>(nb, n, e);
    k_scan3<<<(n + T - 1) / T, T>>>(n);
    k_fill<<<(e + T - 1) / T, T>>>(ei, e);
    if (g > 0) k_gcnt<<<(n + T - 1) / T, T>>>(batch, n);

    // --- layer 1: aggregate 7-wide, then transform+bias+relu ---
    k_agg7<<<(n * 8 + T - 1) / T, T>>>(x, n);
    k_gemm1<<<(n * 128 + T - 1) / T, T>>>(W1, b1, n);

    // --- layer 2: transform (g_H -> g_T), aggregate+bias+relu (g_T -> g_H) ---
    k_gemm<128><<<(n + 63) / 64, 256>>>(W2, n);
    k_agg<128, true, false, true><<<(n * 32 + T - 1) / T, T>>>(b2, nullptr, batch, n);

    // --- layer 3: transform 64-wide (g_H -> g_T), aggregate+bias (+pool) -> out ---
    k_gemm<64><<<(n + 63) / 64, 256>>>(W3, n);
    if (g > 0) {
        k_agg<64, false, true, false><<<(n * 16 + T - 1) / T, T>>>(b3, out, batch, n);
        k_pooldiv<<<(g * OUTF + T - 1) / T, T>>>(out + (size_t)n * OUTF, g);
    } else {
        k_agg<64, false, false, false><<<(n * 16 + T - 1) / T, T>>>(b3, out, batch, n);
    }
}

// round 7
// speedup vs baseline: 1.1024x; 1.0120x over previous
#include <cuda_runtime.h>
#include <stdint.h>

// Problem constants (fixed by the dataset)
#define NMAX   50000
#define EMAX   800000
#define GMAX   64
#define HID    128
#define OUTF   64

// ---------------- device scratch (no allocations allowed) ----------------
__device__ int                    g_cnt[NMAX];
__device__ int                    g_rowptr[NMAX + 1];
__device__ int                    g_pos[NMAX];
__device__ int                    g_blocksum[64];
__device__ int                    g_csr_src[EMAX];
__device__ float                  g_csr_w[EMAX];
__device__ float                  g_dinv[NMAX];
__device__ __align__(16) float    g_T[NMAX * HID];   // GEMM outputs / messages
__device__ __align__(16) float    g_H[NMAX * HID];   // activations
__device__ float                  g_poolsum[GMAX * OUTF];
__device__ int                    g_gcnt[GMAX];

// ---------------- setup kernels ----------------

__global__ void k_zero(int n) {
    int i = blockIdx.x * blockDim.x + threadIdx.x;
    if (i < n) g_cnt[i] = 0;
    if (i < GMAX * OUTF) g_poolsum[i] = 0.f;
    if (i < GMAX) g_gcnt[i] = 0;
}

__global__ void k_hist(const int* __restrict__ ei, int e) {
    int i = blockIdx.x * blockDim.x + threadIdx.x;
    if (i < e) {
        int d = ei[e + i];   // dst row of edge_index [2,E]
        atomicAdd(&g_cnt[d], 1);
    }
}

// ---------------- hierarchical exclusive scan of g_cnt ----------------
__global__ __launch_bounds__(1024)
void k_scan1(int n) {
    __shared__ int warp_sums[32];
    int tid = threadIdx.x, lane = tid & 31, wid = tid >> 5;
    int i = blockIdx.x * 1024 + tid;
    int v = (i < n) ? g_cnt[i] : 0;
    if (i < n) g_dinv[i] = rsqrtf((float)(v + 1));  // +1 self loop
    int x = v;
    #pragma unroll
    for (int o = 1; o < 32; o <<= 1) {
        int y = __shfl_up_sync(0xffffffffu, x, o);
        if (lane >= o) x += y;
    }
    if (lane == 31) warp_sums[wid] = x;
    __syncthreads();
    if (wid == 0) {
        int w = warp_sums[lane];
        #pragma unroll
        for (int o = 1; o < 32; o <<= 1) {
            int y = __shfl_up_sync(0xffffffffu, w, o);
            if (lane >= o) w += y;
        }
        warp_sums[lane] = w;
    }
    __syncthreads();
    int off = (wid > 0) ? warp_sums[wid - 1] : 0;
    if (i < n) g_rowptr[i] = x + off - v;               // local exclusive
    if (tid == 1023) g_blocksum[blockIdx.x] = x + off;  // block total
}

__global__ void k_scan2(int nb, int n, int e_total) {
    __shared__ int ws[2];
    int tid = threadIdx.x, lane = tid & 31, wid = tid >> 5;
    int v = (tid < nb) ? g_blocksum[tid] : 0;
    int x = v;
    #pragma unroll
    for (int o = 1; o < 32; o <<= 1) {
        int y = __shfl_up_sync(0xffffffffu, x, o);
        if (lane >= o) x += y;
    }
    if (lane == 31) ws[wid] = x;
    __syncthreads();
    int off = (wid == 1) ? ws[0] : 0;
    if (tid < 64) g_blocksum[tid] = x + off - v;   // exclusive
    if (tid == 0) g_rowptr[n] = e_total;
}

__global__ void k_scan3(int n) {
    int i = blockIdx.x * blockDim.x + threadIdx.x;
    if (i < n) {
        int r = g_rowptr[i] + g_blocksum[i >> 10];
        g_rowptr[i] = r;
        g_pos[i] = r;
    }
}

__global__ void k_fill(const int* __restrict__ ei, int e) {
    int i = blockIdx.x * blockDim.x + threadIdx.x;
    if (i < e) {
        int s = ei[i];
        int d = ei[e + i];
        int idx = atomicAdd(&g_pos[d], 1);
        g_csr_src[idx] = s;
        g_csr_w[idx]   = g_dinv[s] * g_dinv[d];
    }
}

__global__ void k_gcnt(const int* __restrict__ batch, int n) {
    int i = blockIdx.x * blockDim.x + threadIdx.x;
    if (i < n) atomicAdd(&g_gcnt[batch[i]], 1);
}

// ---------------- layer 1: aggregate raw 7-wide features ----------------
__global__ void k_agg7(const float* __restrict__ x, int n) {
    int gid = blockIdx.x * blockDim.x + threadIdx.x;
    int node = gid >> 3;
    int f = gid & 7;
    if (node >= n) return;
    float di = g_dinv[node];
    float acc = (f < 7) ? x[node * 7 + f] * di * di : 0.f;
    int beg = g_rowptr[node], end = g_rowptr[node + 1];
    for (int e = beg; e < end; ++e) {
        int s = g_csr_src[e];
        float w = g_csr_w[e];
        if (f < 7) acc += w * x[s * 7 + f];
    }
    if (f < 7) g_T[node * 8 + f] = acc;
}

// h1 = relu(m @ W1 + b1), m stride-8 in g_T, out to g_H (N x 128)
__global__ void k_gemm1(const float* __restrict__ W1, const float* __restrict__ b1, int n) {
    int gid = blockIdx.x * blockDim.x + threadIdx.x;
    int node = gid >> 7;
    int c = gid & 127;
    if (node >= n) return;
    const float* m = g_T + node * 8;
    float acc = b1[c];
    #pragma unroll
    for (int k = 0; k < 7; ++k) acc = fmaf(m[k], W1[k * 128 + c], acc);
    g_H[node * 128 + c] = fmaxf(acc, 0.f);
}

// ---------------- dense GEMM: g_T[n,NOUT] = g_H[n,128] @ B[128,NOUT] ----------------
// 8x8 register tiles, consecutive thread rows, 256 threads/block.
template<int NOUT, int BN>
__global__ __launch_bounds__(256)
void k_gemm(const float* __restrict__ B, int n) {
    constexpr int K = 128, KT = 32;
    constexpr int CG = NOUT / 8;        // col groups (8 cols each)
    static_assert(BN == (256 / CG) * 8, "tile mismatch");
    __shared__ float sA[BN][KT + 1];
    __shared__ float sB[KT][NOUT];
    int tid = threadIdx.x;
    int tx = tid % CG;
    int ty = tid / CG;
    int row0 = ty * 8;
    int nodeBase = blockIdx.x * BN;
    float acc[8][8];
    #pragma unroll
    for (int r = 0; r < 8; ++r)
        #pragma unroll
        for (int c = 0; c < 8; ++c) acc[r][c] = 0.f;

    for (int k0 = 0; k0 < K; k0 += KT) {
        #pragma unroll
        for (int t = 0; t < BN * KT / 1024; ++t) {
            int idx = tid + t * 256;
            int r  = idx >> 3;       // / (KT/4)
            int c4 = idx & 7;
            int nd = nodeBase + r;
            float4 v = make_float4(0.f, 0.f, 0.f, 0.f);
            if (nd < n) v = *reinterpret_cast<const float4*>(&g_H[nd * K + k0 + c4 * 4]);
            sA[r][c4 * 4 + 0] = v.x; sA[r][c4 * 4 + 1] = v.y;
            sA[r][c4 * 4 + 2] = v.z; sA[r][c4 * 4 + 3] = v.w;
        }
        #pragma unroll
        for (int t = 0; t < KT * NOUT / 1024; ++t) {
            int idx = tid + t * 256;
            int r  = idx / (NOUT / 4);
            int c4 = idx % (NOUT / 4);
            *reinterpret_cast<float4*>(&sB[r][c4 * 4]) =
                *reinterpret_cast<const float4*>(&B[(k0 + r) * NOUT + c4 * 4]);
        }
        __syncthreads();
        #pragma unroll
        for (int kk = 0; kk < KT; ++kk) {
            float a[8], b[8];
            #pragma unroll
            for (int r = 0; r < 8; ++r) a[r] = sA[row0 + r][kk];
            *reinterpret_cast<float4*>(&b[0]) = *reinterpret_cast<const float4*>(&sB[kk][tx * 8]);
            *reinterpret_cast<float4*>(&b[4]) = *reinterpret_cast<const float4*>(&sB[kk][tx * 8 + 4]);
            #pragma unroll
            for (int r = 0; r < 8; ++r)
                #pragma unroll
                for (int c = 0; c < 8; ++c)
                    acc[r][c] = fmaf(a[r], b[c], acc[r][c]);
        }
        __syncthreads();
    }
    #pragma unroll
    for (int r = 0; r < 8; ++r) {
        int nd = nodeBase + row0 + r;
        if (nd < n) {
            *reinterpret_cast<float4*>(&g_T[nd * NOUT + tx * 8]) =
                make_float4(acc[r][0], acc[r][1], acc[r][2], acc[r][3]);
            *reinterpret_cast<float4*>(&g_T[nd * NOUT + tx * 8 + 4]) =
                make_float4(acc[r][4], acc[r][5], acc[r][6], acc[r][7]);
        }
    }
}

// ---------------- sparse aggregation of transformed features ----------------
template<int F, bool RELU, bool POOL, bool TO_H>
__global__ __launch_bounds__(256)
void k_agg(const float* __restrict__ bias, float* __restrict__ out,
           const int* __restrict__ batch, int n) {
    constexpr int LPN = F / 4;   // float4 lanes per node
    int gid = blockIdx.x * blockDim.x + threadIdx.x;
    int node = gid / LPN;
    int l = gid % LPN;
    if (node >= n) return;
    float di = g_dinv[node];
    float w0 = di * di;
    const float4* T4 = reinterpret_cast<const float4*>(g_T);
    float4 v = T4[node * LPN + l];
    float4 acc = make_float4(v.x * w0, v.y * w0, v.z * w0, v.w * w0);
    int e = g_rowptr[node], end = g_rowptr[node + 1];
    // 4-wide unroll for MLP
    for (; e + 3 < end; e += 4) {
        int s0 = g_csr_src[e],     s1 = g_csr_src[e + 1];
        int s2 = g_csr_src[e + 2], s3 = g_csr_src[e + 3];
        float w1 = g_csr_w[e],     w2 = g_csr_w[e + 1];
        float w3 = g_csr_w[e + 2], w4 = g_csr_w[e + 3];
        float4 t0 = T4[s0 * LPN + l];
        float4 t1 = T4[s1 * LPN + l];
        float4 t2 = T4[s2 * LPN + l];
        float4 t3 = T4[s3 * LPN + l];
        acc.x = fmaf(w1, t0.x, acc.x); acc.y = fmaf(w1, t0.y, acc.y);
        acc.z = fmaf(w1, t0.z, acc.z); acc.w = fmaf(w1, t0.w, acc.w);
        acc.x = fmaf(w2, t1.x, acc.x); acc.y = fmaf(w2, t1.y, acc.y);
        acc.z = fmaf(w2, t1.z, acc.z); acc.w = fmaf(w2, t1.w, acc.w);
        acc.x = fmaf(w3, t2.x, acc.x); acc.y = fmaf(w3, t2.y, acc.y);
        acc.z = fmaf(w3, t2.z, acc.z); acc.w = fmaf(w3, t2.w, acc.w);
        acc.x = fmaf(w4, t3.x, acc.x); acc.y = fmaf(w4, t3.y, acc.y);
        acc.z = fmaf(w4, t3.z, acc.z); acc.w = fmaf(w4, t3.w, acc.w);
    }
    for (; e < end; ++e) {
        int s0 = g_csr_src[e]; float w1 = g_csr_w[e];
        float4 t0 = T4[s0 * LPN + l];
        acc.x = fmaf(w1, t0.x, acc.x); acc.y = fmaf(w1, t0.y, acc.y);
        acc.z = fmaf(w1, t0.z, acc.z); acc.w = fmaf(w1, t0.w, acc.w);
    }
    float4 b = reinterpret_cast<const float4*>(bias)[l];
    acc.x += b.x; acc.y += b.y; acc.z += b.z; acc.w += b.w;
    if (RELU) {
        acc.x = fmaxf(acc.x, 0.f); acc.y = fmaxf(acc.y, 0.f);
        acc.z = fmaxf(acc.z, 0.f); acc.w = fmaxf(acc.w, 0.f);
    }
    if (TO_H)
        reinterpret_cast<float4*>(g_H)[node * LPN + l] = acc;
    else
        reinterpret_cast<float4*>(out)[node * LPN + l] = acc;
    if (POOL) {
        int gidx = batch[node];
        atomicAdd(&g_poolsum[gidx * F + l * 4 + 0], acc.x);
        atomicAdd(&g_poolsum[gidx * F + l * 4 + 1], acc.y);
        atomicAdd(&g_poolsum[gidx * F + l * 4 + 2], acc.z);
        atomicAdd(&g_poolsum[gidx * F + l * 4 + 3], acc.w);
    }
}

__global__ void k_pooldiv(float* __restrict__ out, int g) {
    int i = blockIdx.x * blockDim.x + threadIdx.x;
    if (i < g * OUTF) {
        float c = (float)g_gcnt[i / OUTF];
        out[i] = g_poolsum[i] / fmaxf(c, 1.f);
    }
}

// ---------------- launch ----------------
extern "C" void kernel_launch(void* const* d_in, const int* in_sizes, int n_in,
                              void* d_out, int out_size) {
    const float* x     = (const float*)d_in[0];
    const int*   ei    = (const int*)d_in[1];    // int32 (jax x64 disabled)
    const int*   batch = (const int*)d_in[2];    // int32
    const float* W1 = (const float*)d_in[3];
    const float* b1 = (const float*)d_in[4];
    const float* W2 = (const float*)d_in[5];
    const float* b2 = (const float*)d_in[6];
    const float* W3 = (const float*)d_in[7];
    const float* b3 = (const float*)d_in[8];
    float* out = (float*)d_out;

    int n = in_sizes[0] / 7;
    int e = in_sizes[1] / 2;
    int g = out_size / OUTF - n;
    if (g < 0) g = 0;

    const int T = 256;
    int nb = (n + 1023) / 1024;           // scan blocks (<= 64)
    // --- degree / CSR build ---
    k_zero<<<(n + T - 1) / T, T>>>(n);
    k_hist<<<(e + T - 1) / T, T>>>(ei, e);
    k_scan1<<<nb, 1024>>>(n);             // also computes g_dinv
    k_scan2<<<1, 64>>>(nb, n, e);
    k_scan3<<<(n + T - 1) / T, T>>>(n);
    k_fill<<<(e + T - 1) / T, T>>>(ei, e);
    if (g > 0) k_gcnt<<<(n + T - 1) / T, T>>>(batch, n);

    // --- layer 1: aggregate 7-wide, then transform+bias+relu ---
    k_agg7<<<(n * 8 + T - 1) / T, T>>>(x, n);
    k_gemm1<<<(n * 128 + T - 1) / T, T>>>(W1, b1, n);

    // --- layer 2: transform (g_H -> g_T), aggregate+bias+relu (g_T -> g_H) ---
    k_gemm<128, 128><<<(n + 127) / 128, 256>>>(W2, n);
    k_agg<128, true, false, true><<<(n * 32 + T - 1) / T, T>>>(b2, nullptr, batch, n);

    // --- layer 3: transform 64-wide (g_H -> g_T), aggregate+bias (+pool) -> out ---
    k_gemm<64, 256><<<(n + 255) / 256, 256>>>(W3, n);
    if (g > 0) {
        k_agg<64, false, true, false><<<(n * 16 + T - 1) / T, T>>>(b3, out, batch, n);
        k_pooldiv<<<(g * OUTF + T - 1) / T, T>>>(out + (size_t)n * OUTF, g);
    } else {
        k_agg<64, false, false, false><<<(n * 16 + T - 1) / T, T>>>(b3, out, batch, n);
    }
}

// round 9
// speedup vs baseline: 1.1083x; 1.0053x over previous
#include <cuda_runtime.h>
#include <stdint.h>

// Problem constants (fixed by the dataset)
#define NMAX   50000
#define EMAX   800000
#define GMAX   64
#define HID    128
#define OUTF   64

// ---------------- device scratch (no allocations allowed) ----------------
// NOTE: all of these are zero at module load; k_zero_next re-zeros the ones
// that must be zero at the START of each kernel_launch call (g_cnt,
// g_tilestate, g_poolsum, g_gcnt) at the END of the previous call.
__device__ int                    g_cnt[NMAX];
__device__ unsigned int           g_tilestate[64];   // lookback scan state
__device__ int                    g_rowptr[NMAX + 1];
__device__ int                    g_pos[NMAX];
__device__ int                    g_csr_src[EMAX];
__device__ float                  g_csr_w[EMAX];
__device__ float                  g_dinv[NMAX];
__device__ __align__(16) float    g_T[NMAX * HID];   // GEMM outputs / messages
__device__ __align__(16) float    g_H[NMAX * HID];   // activations
__device__ float                  g_poolsum[GMAX * OUTF];
__device__ int                    g_gcnt[GMAX];

// ---------------- setup: degree histogram + graph-size histogram ----------------
__global__ void k_hist(const int* __restrict__ ei, const int* __restrict__ batch,
                       int e, int n) {
    int i = blockIdx.x * blockDim.x + threadIdx.x;
    if (i < e) atomicAdd(&g_cnt[ei[e + i]], 1);     // dst degrees
    if (i < n) atomicAdd(&g_gcnt[batch[i]], 1);     // nodes per graph
}

// ---------------- single-pass decoupled-lookback exclusive scan ----------------
// writes g_rowptr / g_pos; also computes g_dinv. Tile = 1024 elements.
__global__ __launch_bounds__(1024)
void k_scan_lb(int n, int e_total) {
    __shared__ int warp_sums[32];
    __shared__ int s_prefix;
    int b = blockIdx.x, tid = threadIdx.x, lane = tid & 31, wid = tid >> 5;
    int i = b * 1024 + tid;
    int v = (i < n) ? g_cnt[i] : 0;
    if (i < n) g_dinv[i] = rsqrtf((float)(v + 1));  // +1 self loop
    int x = v;
    #pragma unroll
    for (int o = 1; o < 32; o <<= 1) {
        int y = __shfl_up_sync(0xffffffffu, x, o);
        if (lane >= o) x += y;
    }
    if (lane == 31) warp_sums[wid] = x;
    __syncthreads();
    if (wid == 0) {
        int w = warp_sums[lane];
        #pragma unroll
        for (int o = 1; o < 32; o <<= 1) {
            int y = __shfl_up_sync(0xffffffffu, w, o);
            if (lane >= o) w += y;
        }
        warp_sums[lane] = w;
    }
    __syncthreads();
    int off = (wid > 0) ? warp_sums[wid - 1] : 0;
    int incl = x + off;                       // block-local inclusive
    unsigned total = (unsigned)warp_sums[31]; // block total
    if (tid == 0) {
        if (b == 0) {
            atomicExch(&g_tilestate[0], (2u << 30) | total);
            s_prefix = 0;
        } else {
            atomicExch(&g_tilestate[b], (1u << 30) | total);
            unsigned pfx = 0;
            int p = b - 1;
            while (true) {
                unsigned st = atomicAdd(&g_tilestate[p], 0u);
                unsigned f = st >> 30;
                if (f == 0) continue;            // not yet published: spin
                pfx += st & 0x3FFFFFFFu;
                if (f == 2) break;               // inclusive prefix found
                --p;
            }
            atomicExch(&g_tilestate[b], (2u << 30) | (total + pfx));
            s_prefix = (int)pfx;
        }
    }
    __syncthreads();
    int pfx = s_prefix;
    if (i < n) {
        int r = incl - v + pfx;                  // global exclusive
        g_rowptr[i] = r;
        g_pos[i] = r;
    }
    if (i == n - 1) g_rowptr[n] = e_total;
}

__global__ void k_fill(const int* __restrict__ ei, int e) {
    int i = blockIdx.x * blockDim.x + threadIdx.x;
    if (i < e) {
        int s = ei[i];
        int d = ei[e + i];
        int idx = atomicAdd(&g_pos[d], 1);
        g_csr_src[idx] = s;
        g_csr_w[idx]   = g_dinv[s] * g_dinv[d];
    }
}

// ---------------- fused layer 1: aggregate 7-wide + transform + bias + relu ----
// warp per node: lanes cooperatively gather edges, shfl-reduce the 7-vector,
// then each lane emits 4 columns of relu(m @ W1 + b1) into g_H.
__global__ __launch_bounds__(256)
void k_l1(const float* __restrict__ x, const float* __restrict__ W1,
          const float* __restrict__ b1, int n) {
    int warp = (blockIdx.x * blockDim.x + threadIdx.x) >> 5;
    int lane = threadIdx.x & 31;
    if (warp >= n) return;
    int node = warp;
    float di = g_dinv[node];
    float acc[7];
    if (lane == 0) {
        float w0 = di * di;
        #pragma unroll
        for (int f = 0; f < 7; ++f) acc[f] = x[node * 7 + f] * w0;
    } else {
        #pragma unroll
        for (int f = 0; f < 7; ++f) acc[f] = 0.f;
    }
    int beg = g_rowptr[node], end = g_rowptr[node + 1];
    for (int e = beg + lane; e < end; e += 32) {
        int s = g_csr_src[e];
        float w = g_csr_w[e];
        #pragma unroll
        for (int f = 0; f < 7; ++f) acc[f] = fmaf(w, x[s * 7 + f], acc[f]);
    }
    #pragma unroll
    for (int f = 0; f < 7; ++f)
        #pragma unroll
        for (int o = 16; o > 0; o >>= 1)
            acc[f] += __shfl_xor_sync(0xffffffffu, acc[f], o);
    // every lane now holds the full aggregated 7-vector; emit 4 columns
    int c = lane * 4;
    float4 r = *reinterpret_cast<const float4*>(&b1[c]);
    #pragma unroll
    for (int f = 0; f < 7; ++f) {
        float4 wv = *reinterpret_cast<const float4*>(&W1[f * 128 + c]);
        r.x = fmaf(acc[f], wv.x, r.x); r.y = fmaf(acc[f], wv.y, r.y);
        r.z = fmaf(acc[f], wv.z, r.z); r.w = fmaf(acc[f], wv.w, r.w);
    }
    r.x = fmaxf(r.x, 0.f); r.y = fmaxf(r.y, 0.f);
    r.z = fmaxf(r.z, 0.f); r.w = fmaxf(r.w, 0.f);
    *reinterpret_cast<float4*>(&g_H[node * 128 + c]) = r;
}

// ---------------- dense GEMM: g_T[n,NOUT] = g_H[n,128] @ B[128,NOUT] ----------------
// 8x8 register tiles, consecutive thread rows, 256 threads/block.
template<int NOUT, int BN>
__global__ __launch_bounds__(256)
void k_gemm(const float* __restrict__ B, int n) {
    constexpr int K = 128, KT = 32;
    constexpr int CG = NOUT / 8;        // col groups (8 cols each)
    static_assert(BN == (256 / CG) * 8, "tile mismatch");
    __shared__ float sA[BN][KT + 1];
    __shared__ float sB[KT][NOUT];
    int tid = threadIdx.x;
    int tx = tid % CG;
    int ty = tid / CG;
    int row0 = ty * 8;
    int nodeBase = blockIdx.x * BN;
    float acc[8][8];
    #pragma unroll
    for (int r = 0; r < 8; ++r)
        #pragma unroll
        for (int c = 0; c < 8; ++c) acc[r][c] = 0.f;

    for (int k0 = 0; k0 < K; k0 += KT) {
        #pragma unroll
        for (int t = 0; t < BN * KT / 1024; ++t) {
            int idx = tid + t * 256;
            int r  = idx >> 3;
            int c4 = idx & 7;
            int nd = nodeBase + r;
            float4 v = make_float4(0.f, 0.f, 0.f, 0.f);
            if (nd < n) v = *reinterpret_cast<const float4*>(&g_H[nd * K + k0 + c4 * 4]);
            sA[r][c4 * 4 + 0] = v.x; sA[r][c4 * 4 + 1] = v.y;
            sA[r][c4 * 4 + 2] = v.z; sA[r][c4 * 4 + 3] = v.w;
        }
        #pragma unroll
        for (int t = 0; t < KT * NOUT / 1024; ++t) {
            int idx = tid + t * 256;
            int r  = idx / (NOUT / 4);
            int c4 = idx % (NOUT / 4);
            *reinterpret_cast<float4*>(&sB[r][c4 * 4]) =
                *reinterpret_cast<const float4*>(&B[(k0 + r) * NOUT + c4 * 4]);
        }
        __syncthreads();
        #pragma unroll
        for (int kk = 0; kk < KT; ++kk) {
            float a[8], b[8];
            #pragma unroll
            for (int r = 0; r < 8; ++r) a[r] = sA[row0 + r][kk];
            *reinterpret_cast<float4*>(&b[0]) = *reinterpret_cast<const float4*>(&sB[kk][tx * 8]);
            *reinterpret_cast<float4*>(&b[4]) = *reinterpret_cast<const float4*>(&sB[kk][tx * 8 + 4]);
            #pragma unroll
            for (int r = 0; r < 8; ++r)
                #pragma unroll
                for (int c = 0; c < 8; ++c)
                    acc[r][c] = fmaf(a[r], b[c], acc[r][c]);
        }
        __syncthreads();
    }
    #pragma unroll
    for (int r = 0; r < 8; ++r) {
        int nd = nodeBase + row0 + r;
        if (nd < n) {
            *reinterpret_cast<float4*>(&g_T[nd * NOUT + tx * 8]) =
                make_float4(acc[r][0], acc[r][1], acc[r][2], acc[r][3]);
            *reinterpret_cast<float4*>(&g_T[nd * NOUT + tx * 8 + 4]) =
                make_float4(acc[r][4], acc[r][5], acc[r][6], acc[r][7]);
        }
    }
}

// ---------------- sparse aggregation of transformed features ----------------
template<int F, bool RELU, bool POOL, bool TO_H>
__global__ __launch_bounds__(256)
void k_agg(const float* __restrict__ bias, float* __restrict__ out,
           const int* __restrict__ batch, int n) {
    constexpr int LPN = F / 4;   // float4 lanes per node
    int gid = blockIdx.x * blockDim.x + threadIdx.x;
    int node = gid / LPN;
    int l = gid % LPN;
    if (node >= n) return;
    float di = g_dinv[node];
    float w0 = di * di;
    const float4* T4 = reinterpret_cast<const float4*>(g_T);
    float4 v = T4[node * LPN + l];
    float4 acc = make_float4(v.x * w0, v.y * w0, v.z * w0, v.w * w0);
    int e = g_rowptr[node], end = g_rowptr[node + 1];
    for (; e + 3 < end; e += 4) {
        int s0 = g_csr_src[e],     s1 = g_csr_src[e + 1];
        int s2 = g_csr_src[e + 2], s3 = g_csr_src[e + 3];
        float w1 = g_csr_w[e],     w2 = g_csr_w[e + 1];
        float w3 = g_csr_w[e + 2], w4 = g_csr_w[e + 3];
        float4 t0 = T4[s0 * LPN + l];
        float4 t1 = T4[s1 * LPN + l];
        float4 t2 = T4[s2 * LPN + l];
        float4 t3 = T4[s3 * LPN + l];
        acc.x = fmaf(w1, t0.x, acc.x); acc.y = fmaf(w1, t0.y, acc.y);
        acc.z = fmaf(w1, t0.z, acc.z); acc.w = fmaf(w1, t0.w, acc.w);
        acc.x = fmaf(w2, t1.x, acc.x); acc.y = fmaf(w2, t1.y, acc.y);
        acc.z = fmaf(w2, t1.z, acc.z); acc.w = fmaf(w2, t1.w, acc.w);
        acc.x = fmaf(w3, t2.x, acc.x); acc.y = fmaf(w3, t2.y, acc.y);
        acc.z = fmaf(w3, t2.z, acc.z); acc.w = fmaf(w3, t2.w, acc.w);
        acc.x = fmaf(w4, t3.x, acc.x); acc.y = fmaf(w4, t3.y, acc.y);
        acc.z = fmaf(w4, t3.z, acc.z); acc.w = fmaf(w4, t3.w, acc.w);
    }
    for (; e < end; ++e) {
        int s0 = g_csr_src[e]; float w1 = g_csr_w[e];
        float4 t0 = T4[s0 * LPN + l];
        acc.x = fmaf(w1, t0.x, acc.x); acc.y = fmaf(w1, t0.y, acc.y);
        acc.z = fmaf(w1, t0.z, acc.z); acc.w = fmaf(w1, t0.w, acc.w);
    }
    float4 b = reinterpret_cast<const float4*>(bias)[l];
    acc.x += b.x; acc.y += b.y; acc.z += b.z; acc.w += b.w;
    if (RELU) {
        acc.x = fmaxf(acc.x, 0.f); acc.y = fmaxf(acc.y, 0.f);
        acc.z = fmaxf(acc.z, 0.f); acc.w = fmaxf(acc.w, 0.f);
    }
    if (TO_H)
        reinterpret_cast<float4*>(g_H)[node * LPN + l] = acc;
    else
        reinterpret_cast<float4*>(out)[node * LPN + l] = acc;
    if (POOL) {
        int gidx = batch[node];
        atomicAdd(&g_poolsum[gidx * F + l * 4 + 0], acc.x);
        atomicAdd(&g_poolsum[gidx * F + l * 4 + 1], acc.y);
        atomicAdd(&g_poolsum[gidx * F + l * 4 + 2], acc.z);
        atomicAdd(&g_poolsum[gidx * F + l * 4 + 3], acc.w);
    }
}

__global__ void k_pooldiv(float* __restrict__ out, int g) {
    int i = blockIdx.x * blockDim.x + threadIdx.x;
    if (i < g * OUTF) {
        float c = (float)g_gcnt[i / OUTF];
        out[i] = g_poolsum[i] / fmaxf(c, 1.f);
    }
}

// zero state for the NEXT kernel_launch call (globals start zeroed at load)
__global__ void k_zero_next(int n) {
    int i = blockIdx.x * blockDim.x + threadIdx.x;
    if (i < n) g_cnt[i] = 0;
    if (i < 64) g_tilestate[i] = 0;
    if (i < GMAX * OUTF) g_poolsum[i] = 0.f;
    if (i < GMAX) g_gcnt[i] = 0;
}

// ---------------- launch ----------------
extern "C" void kernel_launch(void* const* d_in, const int* in_sizes, int n_in,
                              void* d_out, int out_size) {
    const float* x     = (const float*)d_in[0];
    const int*   ei    = (const int*)d_in[1];    // int32 (jax x64 disabled)
    const int*   batch = (const int*)d_in[2];    // int32
    const float* W1 = (const float*)d_in[3];
    const float* b1 = (const float*)d_in[4];
    const float* W2 = (const float*)d_in[5];
    const float* b2 = (const float*)d_in[6];
    const float* W3 = (const float*)d_in[7];
    const float* b3 = (const float*)d_in[8];
    float* out = (float*)d_out;

    int n = in_sizes[0] / 7;
    int e = in_sizes[1] / 2;
    int g = out_size / OUTF - n;
    if (g < 0) g = 0;

    const int T = 256;
    int nb = (n + 1023) / 1024;                       // scan tiles (<= 64)

    k_hist<<<(e + T - 1) / T, T>>>(ei, batch, e, n);  // 0
    k_scan_lb<<<nb, 1024>>>(n, e);                    // 1
    k_fill<<<(e + T - 1) / T, T>>>(ei, e);            // 2
    k_l1<<<(n * 32 + T - 1) / T, T>>>(x, W1, b1, n);  // 3  <- profiled launch

    k_gemm<128, 128><<<(n + 127) / 128, 256>>>(W2, n);                     // 4
    k_agg<128, true, false, true><<<(n * 32 + T - 1) / T, T>>>(b2, nullptr, batch, n); // 5

    k_gemm<64, 256><<<(n + 255) / 256, 256>>>(W3, n);                      // 6
    if (g > 0) {
        k_agg<64, false, true, false><<<(n * 16 + T - 1) / T, T>>>(b3, out, batch, n); // 7
        k_pooldiv<<<(g * OUTF + T - 1) / T, T>>>(out + (size_t)n * OUTF, g);           // 8
    } else {
        k_agg<64, false, false, false><<<(n * 16 + T - 1) / T, T>>>(b3, out, batch, n);
    }
    k_zero_next<<<(n + T - 1) / T, T>>>(n);           // 9 (state for next call)
}

// round 10
// speedup vs baseline: 1.3557x; 1.2233x over previous
#include <cuda_runtime.h>
#include <stdint.h>

// Problem constants (fixed by the dataset)
#define NMAX   50000
#define EMAX   800000
#define GMAX   64
#define HID    128
#define OUTF   64

// ---------------- device scratch (no allocations allowed) ----------------
// All zero at module load; k_zero_next re-zeros the ones that must be zero at
// the START of each call (g_cnt, g_tilestate, g_poolsum, g_gcnt) at the END
// of the previous call.
__device__ int                    g_cnt[NMAX];
__device__ unsigned int           g_tilestate[64];   // lookback scan state
__device__ int                    g_rowptr[NMAX + 1];
__device__ int                    g_pos[NMAX];
__device__ int                    g_csr_src[EMAX];
__device__ float                  g_csr_w[EMAX];
__device__ float                  g_dinv[NMAX];
__device__ __align__(16) float    g_X8[NMAX * 8];    // x padded to 8-wide
__device__ __align__(16) float    g_T[NMAX * HID];   // GEMM outputs / messages
__device__ __align__(16) float    g_H[NMAX * HID];   // activations
__device__ float                  g_poolsum[GMAX * OUTF];
__device__ int                    g_gcnt[GMAX];

// ---------------- tf32 helpers ----------------
__device__ __forceinline__ uint32_t f2tf32(float f) {
    uint32_t r;
    asm("cvt.rna.tf32.f32 %0, %1;" : "=r"(r) : "f"(f));
    return r;
}
__device__ __forceinline__ void mma_tf32(float* c, const uint32_t* a,
                                         uint32_t b0, uint32_t b1) {
    asm("mma.sync.aligned.m16n8k8.row.col.f32.tf32.tf32.f32 "
        "{%0,%1,%2,%3}, {%4,%5,%6,%7}, {%8,%9}, {%0,%1,%2,%3};"
        : "+f"(c[0]), "+f"(c[1]), "+f"(c[2]), "+f"(c[3])
        : "r"(a[0]), "r"(a[1]), "r"(a[2]), "r"(a[3]), "r"(b0), "r"(b1));
}

// ---------------- setup: histograms + padded x ----------------
__global__ void k_hist(const int* __restrict__ ei, const int* __restrict__ batch,
                       const float* __restrict__ x, int e, int n) {
    int i = blockIdx.x * blockDim.x + threadIdx.x;
    if (i < e) atomicAdd(&g_cnt[ei[e + i]], 1);     // dst degrees
    if (i < n) {
        atomicAdd(&g_gcnt[batch[i]], 1);            // nodes per graph
        const float* xs = x + i * 7;
        float4* X84 = reinterpret_cast<float4*>(g_X8);
        X84[i * 2]     = make_float4(xs[0], xs[1], xs[2], xs[3]);
        X84[i * 2 + 1] = make_float4(xs[4], xs[5], xs[6], 0.f);
    }
}

// ---------------- single-pass decoupled-lookback exclusive scan ----------------
__global__ __launch_bounds__(1024)
void k_scan_lb(int n, int e_total) {
    __shared__ int warp_sums[32];
    __shared__ int s_prefix;
    int b = blockIdx.x, tid = threadIdx.x, lane = tid & 31, wid = tid >> 5;
    int i = b * 1024 + tid;
    int v = (i < n) ? g_cnt[i] : 0;
    if (i < n) g_dinv[i] = rsqrtf((float)(v + 1));  // +1 self loop
    int x = v;
    #pragma unroll
    for (int o = 1; o < 32; o <<= 1) {
        int y = __shfl_up_sync(0xffffffffu, x, o);
        if (lane >= o) x += y;
    }
    if (lane == 31) warp_sums[wid] = x;
    __syncthreads();
    if (wid == 0) {
        int w = warp_sums[lane];
        #pragma unroll
        for (int o = 1; o < 32; o <<= 1) {
            int y = __shfl_up_sync(0xffffffffu, w, o);
            if (lane >= o) w += y;
        }
        warp_sums[lane] = w;
    }
    __syncthreads();
    int off = (wid > 0) ? warp_sums[wid - 1] : 0;
    int incl = x + off;
    unsigned total = (unsigned)warp_sums[31];
    if (tid == 0) {
        if (b == 0) {
            atomicExch(&g_tilestate[0], (2u << 30) | total);
            s_prefix = 0;
        } else {
            atomicExch(&g_tilestate[b], (1u << 30) | total);
            unsigned pfx = 0;
            int p = b - 1;
            while (true) {
                unsigned st = atomicAdd(&g_tilestate[p], 0u);
                unsigned f = st >> 30;
                if (f == 0) continue;
                pfx += st & 0x3FFFFFFFu;
                if (f == 2) break;
                --p;
            }
            atomicExch(&g_tilestate[b], (2u << 30) | (total + pfx));
            s_prefix = (int)pfx;
        }
    }
    __syncthreads();
    int pfx = s_prefix;
    if (i < n) {
        int r = incl - v + pfx;
        g_rowptr[i] = r;
        g_pos[i] = r;
    }
    if (i == n - 1) g_rowptr[n] = e_total;
}

__global__ void k_fill(const int* __restrict__ ei, int e) {
    int i = blockIdx.x * blockDim.x + threadIdx.x;
    if (i < e) {
        int s = ei[i];
        int d = ei[e + i];
        int idx = atomicAdd(&g_pos[d], 1);
        g_csr_src[idx] = s;
        g_csr_w[idx]   = g_dinv[s] * g_dinv[d];
    }
}

// ---------------- fused layer 1: aggregate 7-wide + transform + bias + relu ----
// warp per node, float4 gathers from padded g_X8.
__global__ __launch_bounds__(256)
void k_l1(const float* __restrict__ W1, const float* __restrict__ b1, int n) {
    int warp = (blockIdx.x * blockDim.x + threadIdx.x) >> 5;
    int lane = threadIdx.x & 31;
    if (warp >= n) return;
    int node = warp;
    const float4* X84 = reinterpret_cast<const float4*>(g_X8);
    float acc[7];
    if (lane == 0) {
        float di = g_dinv[node];
        float w0 = di * di;
        float4 lo = X84[node * 2], hi = X84[node * 2 + 1];
        acc[0] = lo.x * w0; acc[1] = lo.y * w0; acc[2] = lo.z * w0;
        acc[3] = lo.w * w0; acc[4] = hi.x * w0; acc[5] = hi.y * w0;
        acc[6] = hi.z * w0;
    } else {
        #pragma unroll
        for (int f = 0; f < 7; ++f) acc[f] = 0.f;
    }
    int beg = g_rowptr[node], end = g_rowptr[node + 1];
    for (int e = beg + lane; e < end; e += 32) {
        int s = g_csr_src[e];
        float w = g_csr_w[e];
        float4 lo = X84[s * 2], hi = X84[s * 2 + 1];
        acc[0] = fmaf(w, lo.x, acc[0]); acc[1] = fmaf(w, lo.y, acc[1]);
        acc[2] = fmaf(w, lo.z, acc[2]); acc[3] = fmaf(w, lo.w, acc[3]);
        acc[4] = fmaf(w, hi.x, acc[4]); acc[5] = fmaf(w, hi.y, acc[5]);
        acc[6] = fmaf(w, hi.z, acc[6]);
    }
    #pragma unroll
    for (int f = 0; f < 7; ++f)
        #pragma unroll
        for (int o = 16; o > 0; o >>= 1)
            acc[f] += __shfl_xor_sync(0xffffffffu, acc[f], o);
    // every lane holds the aggregated 7-vector; emit 4 output columns
    int c = lane * 4;
    float4 r = *reinterpret_cast<const float4*>(&b1[c]);
    #pragma unroll
    for (int f = 0; f < 7; ++f) {
        float4 wv = *reinterpret_cast<const float4*>(&W1[f * 128 + c]);
        r.x = fmaf(acc[f], wv.x, r.x); r.y = fmaf(acc[f], wv.y, r.y);
        r.z = fmaf(acc[f], wv.z, r.z); r.w = fmaf(acc[f], wv.w, r.w);
    }
    r.x = fmaxf(r.x, 0.f); r.y = fmaxf(r.y, 0.f);
    r.z = fmaxf(r.z, 0.f); r.w = fmaxf(r.w, 0.f);
    *reinterpret_cast<float4*>(&g_H[node * 128 + c]) = r;
}

// ---------------- TF32 tensor-core GEMM: g_T[n,NOUT] = g_H[n,128] @ B ----------
// Block tile 128 x NOUT, 8 warps as 4(m) x 2(n), warp tile 32 x NOUT/2.
// mma.m16n8k8 tf32; smem padded for conflict-free fragment loads.
template<int NOUT>
__global__ __launch_bounds__(256)
void k_gemm_tc(const float* __restrict__ Bw, int n) {
    constexpr int K = 128, KT = 32, BM = 128;
    constexpr int WN = NOUT / 2;       // warp n extent
    constexpr int NF = WN / 8;         // n fragments per warp (8 or 4)
    constexpr int SBS = NOUT + 4;      // sB stride
    __shared__ uint32_t sA[BM][KT + 4];  // stride 36: bank = 4*row+k
    __shared__ uint32_t sB[KT][SBS];     // bank = 4*k+n
    int tid = threadIdx.x;
    int w = tid >> 5, lane = tid & 31;
    int mw = w >> 1, nw = w & 1;
    int g = lane >> 2, t = lane & 3;   // groupID, threadInGroup
    int nodeBase = blockIdx.x * BM;
    float acc[2][NF][4];
    #pragma unroll
    for (int mf = 0; mf < 2; ++mf)
        #pragma unroll
        for (int nf = 0; nf < NF; ++nf)
            #pragma unroll
            for (int i = 0; i < 4; ++i) acc[mf][nf][i] = 0.f;

    for (int k0 = 0; k0 < K; k0 += KT) {
        // A tile: 128x32 floats = 1024 float4 over 256 threads
        #pragma unroll
        for (int it = 0; it < 4; ++it) {
            int idx = tid + it * 256;
            int r = idx >> 3, c4 = idx & 7;
            int nd = nodeBase + r;
            float4 v = make_float4(0.f, 0.f, 0.f, 0.f);
            if (nd < n) v = *reinterpret_cast<const float4*>(&g_H[nd * K + k0 + c4 * 4]);
            uint4 u = make_uint4(f2tf32(v.x), f2tf32(v.y), f2tf32(v.z), f2tf32(v.w));
            *reinterpret_cast<uint4*>(&sA[r][c4 * 4]) = u;
        }
        // B tile: KT x NOUT
        #pragma unroll
        for (int it = 0; it < KT * NOUT / 1024; ++it) {
            int idx = tid + it * 256;
            int r = idx / (NOUT / 4), c4 = idx % (NOUT / 4);
            float4 v = *reinterpret_cast<const float4*>(&Bw[(k0 + r) * NOUT + c4 * 4]);
            uint4 u = make_uint4(f2tf32(v.x), f2tf32(v.y), f2tf32(v.z), f2tf32(v.w));
            *reinterpret_cast<uint4*>(&sB[r][c4 * 4]) = u;
        }
        __syncthreads();
        #pragma unroll
        for (int ks = 0; ks < KT; ks += 8) {
            uint32_t a[2][4];
            #pragma unroll
            for (int mf = 0; mf < 2; ++mf) {
                int rb = mw * 32 + mf * 16;
                a[mf][0] = sA[rb + g][ks + t];
                a[mf][1] = sA[rb + g + 8][ks + t];
                a[mf][2] = sA[rb + g][ks + t + 4];
                a[mf][3] = sA[rb + g + 8][ks + t + 4];
            }
            #pragma unroll
            for (int nf = 0; nf < NF; ++nf) {
                int nb = nw * WN + nf * 8;
                uint32_t b0 = sB[ks + t][nb + g];
                uint32_t b1 = sB[ks + t + 4][nb + g];
                mma_tf32(acc[0][nf], a[0], b0, b1);
                mma_tf32(acc[1][nf], a[1], b0, b1);
            }
        }
        __syncthreads();
    }
    // epilogue: c0/c1 at (row+g, nb+2t), c2/c3 at (row+g+8, nb+2t)
    #pragma unroll
    for (int mf = 0; mf < 2; ++mf) {
        int rowB = nodeBase + mw * 32 + mf * 16;
        #pragma unroll
        for (int nf = 0; nf < NF; ++nf) {
            int col = nw * WN + nf * 8 + t * 2;
            int r0 = rowB + g, r1 = rowB + g + 8;
            if (r0 < n)
                *reinterpret_cast<float2*>(&g_T[r0 * NOUT + col]) =
                    make_float2(acc[mf][nf][0], acc[mf][nf][1]);
            if (r1 < n)
                *reinterpret_cast<float2*>(&g_T[r1 * NOUT + col]) =
                    make_float2(acc[mf][nf][2], acc[mf][nf][3]);
        }
    }
}

// ---------------- sparse aggregation of transformed features ----------------
template<int F, bool RELU, bool POOL, bool TO_H>
__global__ __launch_bounds__(256)
void k_agg(const float* __restrict__ bias, float* __restrict__ out,
           const int* __restrict__ batch, int n) {
    constexpr int LPN = F / 4;
    int gid = blockIdx.x * blockDim.x + threadIdx.x;
    int node = gid / LPN;
    int l = gid % LPN;
    if (node >= n) return;
    float di = g_dinv[node];
    float w0 = di * di;
    const float4* T4 = reinterpret_cast<const float4*>(g_T);
    float4 v = T4[node * LPN + l];
    float4 acc = make_float4(v.x * w0, v.y * w0, v.z * w0, v.w * w0);
    int e = g_rowptr[node], end = g_rowptr[node + 1];
    for (; e + 3 < end; e += 4) {
        int s0 = g_csr_src[e],     s1 = g_csr_src[e + 1];
        int s2 = g_csr_src[e + 2], s3 = g_csr_src[e + 3];
        float w1 = g_csr_w[e],     w2 = g_csr_w[e + 1];
        float w3 = g_csr_w[e + 2], w4 = g_csr_w[e + 3];
        float4 t0 = T4[s0 * LPN + l];
        float4 t1 = T4[s1 * LPN + l];
        float4 t2 = T4[s2 * LPN + l];
        float4 t3 = T4[s3 * LPN + l];
        acc.x = fmaf(w1, t0.x, acc.x); acc.y = fmaf(w1, t0.y, acc.y);
        acc.z = fmaf(w1, t0.z, acc.z); acc.w = fmaf(w1, t0.w, acc.w);
        acc.x = fmaf(w2, t1.x, acc.x); acc.y = fmaf(w2, t1.y, acc.y);
        acc.z = fmaf(w2, t1.z, acc.z); acc.w = fmaf(w2, t1.w, acc.w);
        acc.x = fmaf(w3, t2.x, acc.x); acc.y = fmaf(w3, t2.y, acc.y);
        acc.z = fmaf(w3, t2.z, acc.z); acc.w = fmaf(w3, t2.w, acc.w);
        acc.x = fmaf(w4, t3.x, acc.x); acc.y = fmaf(w4, t3.y, acc.y);
        acc.z = fmaf(w4, t3.z, acc.z); acc.w = fmaf(w4, t3.w, acc.w);
    }
    for (; e < end; ++e) {
        int s0 = g_csr_src[e]; float w1 = g_csr_w[e];
        float4 t0 = T4[s0 * LPN + l];
        acc.x = fmaf(w1, t0.x, acc.x); acc.y = fmaf(w1, t0.y, acc.y);
        acc.z = fmaf(w1, t0.z, acc.z); acc.w = fmaf(w1, t0.w, acc.w);
    }
    float4 b = reinterpret_cast<const float4*>(bias)[l];
    acc.x += b.x; acc.y += b.y; acc.z += b.z; acc.w += b.w;
    if (RELU) {
        acc.x = fmaxf(acc.x, 0.f); acc.y = fmaxf(acc.y, 0.f);
        acc.z = fmaxf(acc.z, 0.f); acc.w = fmaxf(acc.w, 0.f);
    }
    if (TO_H)
        reinterpret_cast<float4*>(g_H)[node * LPN + l] = acc;
    else
        reinterpret_cast<float4*>(out)[node * LPN + l] = acc;
    if (POOL) {
        int gidx = batch[node];
        atomicAdd(&g_poolsum[gidx * F + l * 4 + 0], acc.x);
        atomicAdd(&g_poolsum[gidx * F + l * 4 + 1], acc.y);
        atomicAdd(&g_poolsum[gidx * F + l * 4 + 2], acc.z);
        atomicAdd(&g_poolsum[gidx * F + l * 4 + 3], acc.w);
    }
}

__global__ void k_pooldiv(float* __restrict__ out, int g) {
    int i = blockIdx.x * blockDim.x + threadIdx.x;
    if (i < g * OUTF) {
        float c = (float)g_gcnt[i / OUTF];
        out[i] = g_poolsum[i] / fmaxf(c, 1.f);
    }
}

// zero state for the NEXT kernel_launch call (globals start zeroed at load)
__global__ void k_zero_next(int n) {
    int i = blockIdx.x * blockDim.x + threadIdx.x;
    if (i < n) g_cnt[i] = 0;
    if (i < 64) g_tilestate[i] = 0;
    if (i < GMAX * OUTF) g_poolsum[i] = 0.f;
    if (i < GMAX) g_gcnt[i] = 0;
}

// ---------------- launch ----------------
extern "C" void kernel_launch(void* const* d_in, const int* in_sizes, int n_in,
                              void* d_out, int out_size) {
    const float* x     = (const float*)d_in[0];
    const int*   ei    = (const int*)d_in[1];    // int32 (jax x64 disabled)
    const int*   batch = (const int*)d_in[2];    // int32
    const float* W1 = (const float*)d_in[3];
    const float* b1 = (const float*)d_in[4];
    const float* W2 = (const float*)d_in[5];
    const float* b2 = (const float*)d_in[6];
    const float* W3 = (const float*)d_in[7];
    const float* b3 = (const float*)d_in[8];
    float* out = (float*)d_out;

    int n = in_sizes[0] / 7;
    int e = in_sizes[1] / 2;
    int g = out_size / OUTF - n;
    if (g < 0) g = 0;

    const int T = 256;
    int nb = (n + 1023) / 1024;                         // scan tiles (<= 64)

    k_hist<<<(e + T - 1) / T, T>>>(ei, batch, x, e, n); // 0
    k_scan_lb<<<nb, 1024>>>(n, e);                      // 1
    k_fill<<<(e + T - 1) / T, T>>>(ei, e);              // 2
    k_l1<<<(n * 32 + T - 1) / T, T>>>(W1, b1, n);       // 3  <- profiled launch

    k_gemm_tc<128><<<(n + 127) / 128, 256>>>(W2, n);    // 4
    k_agg<128, true, false, true><<<(n * 32 + T - 1) / T, T>>>(b2, nullptr, batch, n); // 5

    k_gemm_tc<64><<<(n + 127) / 128, 256>>>(W3, n);     // 6
    if (g > 0) {
        k_agg<64, false, true, false><<<(n * 16 + T - 1) / T, T>>>(b3, out, batch, n); // 7
        k_pooldiv<<<(g * OUTF + T - 1) / T, T>>>(out + (size_t)n * OUTF, g);           // 8
    } else {
        k_agg<64, false, false, false><<<(n * 16 + T - 1) / T, T>>>(b3, out, batch, n);
    }
    k_zero_next<<<(n + T - 1) / T, T>>>(n);             // 9
}

// round 12
// speedup vs baseline: 1.4524x; 1.0713x over previous
#include <cuda_runtime.h>
#include <stdint.h>

// Problem constants (fixed by the dataset)
#define NMAX   50000
#define EMAX   800000
#define GMAX   64
#define HID    128
#define OUTF   64

// ---------------- device scratch (no allocations allowed) ----------------
// All zero at module load. Self-cleaning: every kernel that consumes
// call-scoped state zeroes it for the next call (g_cnt in k_scan_lb,
// g_tilestate in k_fill, g_poolsum/g_gcnt in k_pooldiv).
__device__ int                    g_cnt[NMAX];
__device__ unsigned int           g_tilestate[64];   // lookback scan state
__device__ int                    g_rowptr[NMAX + 1];
__device__ int                    g_pos[NMAX];
__device__ int                    g_csr_src[EMAX];
__device__ float                  g_dinv[NMAX];
__device__ __align__(16) float    g_X8[NMAX * 8];    // dinv[i]*x[i], padded to 8
__device__ __align__(16) float    g_T[NMAX * HID];   // dinv-scaled GEMM outputs
__device__ __align__(16) float    g_H[NMAX * HID];   // activations
__device__ float                  g_poolsum[GMAX * OUTF];
__device__ int                    g_gcnt[GMAX];

// ---------------- tf32 helpers ----------------
__device__ __forceinline__ uint32_t f2tf32(float f) {
    uint32_t r;
    asm("cvt.rna.tf32.f32 %0, %1;" : "=r"(r) : "f"(f));
    return r;
}
__device__ __forceinline__ void mma_tf32(float* c, const uint32_t* a,
                                         uint32_t b0, uint32_t b1) {
    asm("mma.sync.aligned.m16n8k8.row.col.f32.tf32.tf32.f32 "
        "{%0,%1,%2,%3}, {%4,%5,%6,%7}, {%8,%9}, {%0,%1,%2,%3};"
        : "+f"(c[0]), "+f"(c[1]), "+f"(c[2]), "+f"(c[3])
        : "r"(a[0]), "r"(a[1]), "r"(a[2]), "r"(a[3]), "r"(b0), "r"(b1));
}

// ---------------- setup: degree + graph-size histograms ----------------
__global__ void k_hist(const int* __restrict__ ei, const int* __restrict__ batch,
                       int e, int n) {
    int i = blockIdx.x * blockDim.x + threadIdx.x;
    if (i < e) atomicAdd(&g_cnt[ei[e + i]], 1);     // dst degrees
    if (i < n) atomicAdd(&g_gcnt[batch[i]], 1);     // nodes per graph
}

// ---------------- single-pass decoupled-lookback exclusive scan --------------
// Also computes g_dinv, writes pre-scaled g_X8 = dinv*x, and zeroes g_cnt.
__global__ __launch_bounds__(1024)
void k_scan_lb(const float* __restrict__ x, int n, int e_total) {
    __shared__ int warp_sums[32];
    __shared__ int s_prefix;
    int b = blockIdx.x, tid = threadIdx.x, lane = tid & 31, wid = tid >> 5;
    int i = b * 1024 + tid;
    int v = (i < n) ? g_cnt[i] : 0;
    if (i < n) {
        float di = rsqrtf((float)(v + 1));          // +1 self loop
        g_dinv[i] = di;
        const float* xs = x + i * 7;
        float4* X84 = reinterpret_cast<float4*>(g_X8);
        X84[i * 2]     = make_float4(xs[0] * di, xs[1] * di, xs[2] * di, xs[3] * di);
        X84[i * 2 + 1] = make_float4(xs[4] * di, xs[5] * di, xs[6] * di, 0.f);
        g_cnt[i] = 0;                               // reset for next call
    }
    int xval = v;
    #pragma unroll
    for (int o = 1; o < 32; o <<= 1) {
        int y = __shfl_up_sync(0xffffffffu, xval, o);
        if (lane >= o) xval += y;
    }
    if (lane == 31) warp_sums[wid] = xval;
    __syncthreads();
    if (wid == 0) {
        int w = warp_sums[lane];
        #pragma unroll
        for (int o = 1; o < 32; o <<= 1) {
            int y = __shfl_up_sync(0xffffffffu, w, o);
            if (lane >= o) w += y;
        }
        warp_sums[lane] = w;
    }
    __syncthreads();
    int off = (wid > 0) ? warp_sums[wid - 1] : 0;
    int incl = xval + off;
    unsigned total = (unsigned)warp_sums[31];
    if (tid == 0) {
        if (b == 0) {
            atomicExch(&g_tilestate[0], (2u << 30) | total);
            s_prefix = 0;
        } else {
            atomicExch(&g_tilestate[b], (1u << 30) | total);
            unsigned pfx = 0;
            int p = b - 1;
            while (true) {
                unsigned st = atomicAdd(&g_tilestate[p], 0u);
                unsigned f = st >> 30;
                if (f == 0) continue;
                pfx += st & 0x3FFFFFFFu;
                if (f == 2) break;
                --p;
            }
            atomicExch(&g_tilestate[b], (2u << 30) | (total + pfx));
            s_prefix = (int)pfx;
        }
    }
    __syncthreads();
    int pfx = s_prefix;
    if (i < n) {
        int r = incl - v + pfx;
        g_rowptr[i] = r;
        g_pos[i] = r;
    }
    if (i == n - 1) g_rowptr[n] = e_total;
}

// CSR fill: src indices only (weights folded into node scaling).
// Also resets tilestate for the next call.
__global__ void k_fill(const int* __restrict__ ei, int e) {
    if (blockIdx.x == 0 && threadIdx.x < 64) g_tilestate[threadIdx.x] = 0;
    int i = blockIdx.x * blockDim.x + threadIdx.x;
    if (i < e) {
        int s = ei[i];
        int d = ei[e + i];
        int idx = atomicAdd(&g_pos[d], 1);
        g_csr_src[idx] = s;
    }
}

// ---------------- fused layer 1: gather-sum + transform + bias + relu --------
// warp per node; unweighted sum of pre-scaled X8 rows, then *dinv_i, @W1.
__global__ __launch_bounds__(256)
void k_l1(const float* __restrict__ W1, const float* __restrict__ b1, int n) {
    int warp = (blockIdx.x * blockDim.x + threadIdx.x) >> 5;
    int lane = threadIdx.x & 31;
    if (warp >= n) return;
    int node = warp;
    const float4* X84 = reinterpret_cast<const float4*>(g_X8);
    float acc[7];
    if (lane == 0) {
        float4 lo = X84[node * 2], hi = X84[node * 2 + 1];
        acc[0] = lo.x; acc[1] = lo.y; acc[2] = lo.z; acc[3] = lo.w;
        acc[4] = hi.x; acc[5] = hi.y; acc[6] = hi.z;
    } else {
        #pragma unroll
        for (int f = 0; f < 7; ++f) acc[f] = 0.f;
    }
    int beg = g_rowptr[node], end = g_rowptr[node + 1];
    for (int e = beg + lane; e < end; e += 32) {
        int s = g_csr_src[e];
        float4 lo = X84[s * 2], hi = X84[s * 2 + 1];
        acc[0] += lo.x; acc[1] += lo.y; acc[2] += lo.z; acc[3] += lo.w;
        acc[4] += hi.x; acc[5] += hi.y; acc[6] += hi.z;
    }
    #pragma unroll
    for (int f = 0; f < 7; ++f)
        #pragma unroll
        for (int o = 16; o > 0; o >>= 1)
            acc[f] += __shfl_xor_sync(0xffffffffu, acc[f], o);
    float di = g_dinv[node];
    #pragma unroll
    for (int f = 0; f < 7; ++f) acc[f] *= di;
    int c = lane * 4;
    float4 r = *reinterpret_cast<const float4*>(&b1[c]);
    #pragma unroll
    for (int f = 0; f < 7; ++f) {
        float4 wv = *reinterpret_cast<const float4*>(&W1[f * 128 + c]);
        r.x = fmaf(acc[f], wv.x, r.x); r.y = fmaf(acc[f], wv.y, r.y);
        r.z = fmaf(acc[f], wv.z, r.z); r.w = fmaf(acc[f], wv.w, r.w);
    }
    r.x = fmaxf(r.x, 0.f); r.y = fmaxf(r.y, 0.f);
    r.z = fmaxf(r.z, 0.f); r.w = fmaxf(r.w, 0.f);
    *reinterpret_cast<float4*>(&g_H[node * 128 + c]) = r;
}

// ---------------- TF32 tensor-core GEMM: g_T[r] = dinv[r] * (g_H[r] @ B) -----
template<int NOUT>
__global__ __launch_bounds__(256)
void k_gemm_tc(const float* __restrict__ Bw, int n) {
    constexpr int K = 128, KT = 32, BM = 128;
    constexpr int WN = NOUT / 2;
    constexpr int NF = WN / 8;
    constexpr int SBS = NOUT + 4;
    __shared__ uint32_t sA[BM][KT + 4];
    __shared__ uint32_t sB[KT][SBS];
    int tid = threadIdx.x;
    int w = tid >> 5, lane = tid & 31;
    int mw = w >> 1, nw = w & 1;
    int g = lane >> 2, t = lane & 3;
    int nodeBase = blockIdx.x * BM;
    float acc[2][NF][4];
    #pragma unroll
    for (int mf = 0; mf < 2; ++mf)
        #pragma unroll
        for (int nf = 0; nf < NF; ++nf)
            #pragma unroll
            for (int i = 0; i < 4; ++i) acc[mf][nf][i] = 0.f;

    for (int k0 = 0; k0 < K; k0 += KT) {
        #pragma unroll
        for (int it = 0; it < 4; ++it) {
            int idx = tid + it * 256;
            int r = idx >> 3, c4 = idx & 7;
            int nd = nodeBase + r;
            float4 v = make_float4(0.f, 0.f, 0.f, 0.f);
            if (nd < n) v = *reinterpret_cast<const float4*>(&g_H[nd * K + k0 + c4 * 4]);
            uint4 u = make_uint4(f2tf32(v.x), f2tf32(v.y), f2tf32(v.z), f2tf32(v.w));
            *reinterpret_cast<uint4*>(&sA[r][c4 * 4]) = u;
        }
        #pragma unroll
        for (int it = 0; it < KT * NOUT / 1024; ++it) {
            int idx = tid + it * 256;
            int r = idx / (NOUT / 4), c4 = idx % (NOUT / 4);
            float4 v = *reinterpret_cast<const float4*>(&Bw[(k0 + r) * NOUT + c4 * 4]);
            uint4 u = make_uint4(f2tf32(v.x), f2tf32(v.y), f2tf32(v.z), f2tf32(v.w));
            *reinterpret_cast<uint4*>(&sB[r][c4 * 4]) = u;
        }
        __syncthreads();
        #pragma unroll
        for (int ks = 0; ks < KT; ks += 8) {
            uint32_t a[2][4];
            #pragma unroll
            for (int mf = 0; mf < 2; ++mf) {
                int rb = mw * 32 + mf * 16;
                a[mf][0] = sA[rb + g][ks + t];
                a[mf][1] = sA[rb + g + 8][ks + t];
                a[mf][2] = sA[rb + g][ks + t + 4];
                a[mf][3] = sA[rb + g + 8][ks + t + 4];
            }
            #pragma unroll
            for (int nf = 0; nf < NF; ++nf) {
                int nb = nw * WN + nf * 8;
                uint32_t b0 = sB[ks + t][nb + g];
                uint32_t b1 = sB[ks + t + 4][nb + g];
                mma_tf32(acc[0][nf], a[0], b0, b1);
                mma_tf32(acc[1][nf], a[1], b0, b1);
            }
        }
        __syncthreads();
    }
    #pragma unroll
    for (int mf = 0; mf < 2; ++mf) {
        int rowB = nodeBase + mw * 32 + mf * 16;
        int r0 = rowB + g, r1 = rowB + g + 8;
        float s0 = (r0 < n) ? g_dinv[r0] : 0.f;
        float s1 = (r1 < n) ? g_dinv[r1] : 0.f;
        #pragma unroll
        for (int nf = 0; nf < NF; ++nf) {
            int col = nw * WN + nf * 8 + t * 2;
            if (r0 < n)
                *reinterpret_cast<float2*>(&g_T[r0 * NOUT + col]) =
                    make_float2(acc[mf][nf][0] * s0, acc[mf][nf][1] * s0);
            if (r1 < n)
                *reinterpret_cast<float2*>(&g_T[r1 * NOUT + col]) =
                    make_float2(acc[mf][nf][2] * s1, acc[mf][nf][3] * s1);
        }
    }
}

// ---------------- sparse aggregation: out = dinv_i*(T'[i]+sum T'[s]) + b ----
template<int F, bool RELU, bool POOL, bool TO_H>
__global__ __launch_bounds__(256)
void k_agg(const float* __restrict__ bias, float* __restrict__ out,
           const int* __restrict__ batch, int n) {
    constexpr int LPN = F / 4;
    int gid = blockIdx.x * blockDim.x + threadIdx.x;
    int node = gid / LPN;
    int l = gid % LPN;
    if (node >= n) return;
    const float4* T4 = reinterpret_cast<const float4*>(g_T);
    float4 acc = T4[node * LPN + l];                // self term (pre-scaled)
    int e = g_rowptr[node], end = g_rowptr[node + 1];
    for (; e + 3 < end; e += 4) {
        int s0 = g_csr_src[e],     s1 = g_csr_src[e + 1];
        int s2 = g_csr_src[e + 2], s3 = g_csr_src[e + 3];
        float4 t0 = T4[s0 * LPN + l];
        float4 t1 = T4[s1 * LPN + l];
        float4 t2 = T4[s2 * LPN + l];
        float4 t3 = T4[s3 * LPN + l];
        acc.x += t0.x + t1.x; acc.y += t0.y + t1.y;
        acc.z += t0.z + t1.z; acc.w += t0.w + t1.w;
        acc.x += t2.x + t3.x; acc.y += t2.y + t3.y;
        acc.z += t2.z + t3.z; acc.w += t2.w + t3.w;
    }
    for (; e < end; ++e) {
        int s0 = g_csr_src[e];
        float4 t0 = T4[s0 * LPN + l];
        acc.x += t0.x; acc.y += t0.y; acc.z += t0.z; acc.w += t0.w;
    }
    float di = g_dinv[node];
    float4 b = reinterpret_cast<const float4*>(bias)[l];
    acc.x = fmaf(di, acc.x, b.x); acc.y = fmaf(di, acc.y, b.y);
    acc.z = fmaf(di, acc.z, b.z); acc.w = fmaf(di, acc.w, b.w);
    if (RELU) {
        acc.x = fmaxf(acc.x, 0.f); acc.y = fmaxf(acc.y, 0.f);
        acc.z = fmaxf(acc.z, 0.f); acc.w = fmaxf(acc.w, 0.f);
    }
    if (TO_H)
        reinterpret_cast<float4*>(g_H)[node * LPN + l] = acc;
    else
        reinterpret_cast<float4*>(out)[node * LPN + l] = acc;
    if (POOL) {
        int gidx = batch[node];
        atomicAdd(&g_poolsum[gidx * F + l * 4 + 0], acc.x);
        atomicAdd(&g_poolsum[gidx * F + l * 4 + 1], acc.y);
        atomicAdd(&g_poolsum[gidx * F + l * 4 + 2], acc.z);
        atomicAdd(&g_poolsum[gidx * F + l * 4 + 3], acc.w);
    }
}

// pooled output + self-zero of poolsum/gcnt for the next call.
// OUTF=64 divides 256 => each group's 64 threads live in one block.
__global__ void k_pooldiv(float* __restrict__ out, int g) {
    int i = blockIdx.x * blockDim.x + threadIdx.x;
    bool act = i < g * OUTF;
    float c = 1.f, s = 0.f;
    if (act) {
        c = (float)g_gcnt[i / OUTF];
        s = g_poolsum[i];
    }
    __syncthreads();                    // all reads done before zeroing
    if (act) {
        out[i] = s / fmaxf(c, 1.f);
        g_poolsum[i] = 0.f;
        if ((i & (OUTF - 1)) == 0) g_gcnt[i / OUTF] = 0;
    }
}

// ---------------- launch ----------------
extern "C" void kernel_launch(void* const* d_in, const int* in_sizes, int n_in,
                              void* d_out, int out_size) {
    const float* x     = (const float*)d_in[0];
    const int*   ei    = (const int*)d_in[1];    // int32 (jax x64 disabled)
    const int*   batch = (const int*)d_in[2];    // int32
    const float* W1 = (const float*)d_in[3];
    const float* b1 = (const float*)d_in[4];
    const float* W2 = (const float*)d_in[5];
    const float* b2 = (const float*)d_in[6];
    const float* W3 = (const float*)d_in[7];
    const float* b3 = (const float*)d_in[8];
    float* out = (float*)d_out;

    int n = in_sizes[0] / 7;
    int e = in_sizes[1] / 2;
    int g = out_size / OUTF - n;
    if (g < 0) g = 0;

    const int T = 256;
    int nb = (n + 1023) / 1024;                         // scan tiles (<= 64)

    k_hist<<<(e + T - 1) / T, T>>>(ei, batch, e, n);    // 0
    k_scan_lb<<<nb, 1024>>>(x, n, e);                   // 1
    k_fill<<<(e + T - 1) / T, T>>>(ei, e);              // 2
    k_l1<<<(n * 32 + T - 1) / T, T>>>(W1, b1, n);       // 3  <- profiled launch

    k_gemm_tc<128><<<(n + 127) / 128, 256>>>(W2, n);    // 4
    k_agg<128, true, false, true><<<(n * 32 + T - 1) / T, T>>>(b2, nullptr, batch, n); // 5

    k_gemm_tc<64><<<(n + 127) / 128, 256>>>(W3, n);     // 6
    if (g > 0) {
        k_agg<64, false, true, false><<<(n * 16 + T - 1) / T, T>>>(b3, out, batch, n); // 7
        k_pooldiv<<<(g * OUTF + T - 1) / T, T>>>(out + (size_t)n * OUTF, g);           // 8
    } else {
        k_agg<64, false, false, false><<<(n * 16 + T - 1) / T, T>>>(b3, out, batch, n);
    }
}